// round 14
// baseline (speedup 1.0000x reference)
#include <cuda_runtime.h>
#include <cuda_bf16.h>
#include <math.h>

// Problem dims
#define Hn 512
#define Dn 128
#define Nn 64
#define Tn 512

// K3: 16 clusters x 8 CTAs; each cluster runs TWO interleaved 2-seq chains.
#define K3_CL 8
#define AP    516                 // buf row stride (floats)
// per-chain-phase incoming: 8 ranks * 64 b64 messages * 8B
#define RX_BYTES 4096u

// ---------------- device scratch (static globals: no allocation) -------------
__device__ float g_E[(size_t)Tn * Nn * Hn];   // emit, then exp(emit - m); [t][n][h]
__device__ float g_M[Tn * Nn];                // rowmax m[t][n]
__device__ float g_Wt[Dn * Hn];               // W^T: [d][h]
__device__ float g_bias[Hn];

// ---------------- helpers -----------------------------------------------------
__device__ __forceinline__ unsigned long long ffma2(unsigned long long a,
                                                    unsigned long long b,
                                                    unsigned long long c) {
    unsigned long long d;
    asm("fma.rn.f32x2 %0, %1, %2, %3;" : "=l"(d) : "l"(a), "l"(b), "l"(c));
    return d;
}
__device__ __forceinline__ unsigned long long fadd2(unsigned long long a,
                                                    unsigned long long b) {
    unsigned long long d;
    asm("add.rn.f32x2 %0, %1, %2;" : "=l"(d) : "l"(a), "l"(b));
    return d;
}
__device__ __forceinline__ float2 up2(unsigned long long v) {
    float2 r;
    asm("mov.b64 {%0, %1}, %2;" : "=f"(r.x), "=f"(r.y) : "l"(v));
    return r;
}
__device__ __forceinline__ unsigned long long pack2(float lo, float hi) {
    unsigned long long v;
    asm("mov.b64 %0, {%1, %2};" : "=l"(v) : "f"(lo), "f"(hi));
    return v;
}
__device__ __forceinline__ unsigned smem_u32(const void* p) {
    return (unsigned)__cvta_generic_to_shared(p);
}
__device__ __forceinline__ unsigned mapa_rank(unsigned saddr, unsigned rank) {
    unsigned r;
    asm("mapa.shared::cluster.u32 %0, %1, %2;" : "=r"(r) : "r"(saddr), "r"(rank));
    return r;
}
__device__ __forceinline__ void st_async_b64(unsigned laddr, unsigned lmbar,
                                             unsigned rank, unsigned long long v) {
    unsigned ra = mapa_rank(laddr, rank);
    unsigned rb = mapa_rank(lmbar, rank);
    asm volatile(
        "st.async.shared::cluster.mbarrier::complete_tx::bytes.b64 [%0], %1, [%2];"
        :: "r"(ra), "l"(v), "r"(rb) : "memory");
}
__device__ __forceinline__ void mbar_init(unsigned mbar, unsigned count) {
    asm volatile("mbarrier.init.shared.b64 [%0], %1;" :: "r"(mbar), "r"(count) : "memory");
}
__device__ __forceinline__ void mbar_expect(unsigned mbar, unsigned bytes) {
    asm volatile("mbarrier.arrive.expect_tx.shared.b64 _, [%0], %1;"
                 :: "r"(mbar), "r"(bytes) : "memory");
}
__device__ __forceinline__ void mbar_wait(unsigned mbar, unsigned parity) {
    asm volatile(
        "{\n\t.reg .pred P1;\n\t"
        "WL_%=:\n\t"
        "mbarrier.try_wait.parity.acquire.cluster.shared::cta.b64 P1, [%0], %1, 0x989680;\n\t"
        "@P1 bra.uni WD_%=;\n\t"
        "bra.uni WL_%=;\n\t"
        "WD_%=:\n\t}"
        :: "r"(mbar), "r"(parity) : "memory");
}
__device__ __forceinline__ void cluster_sync_hw() {
    asm volatile("barrier.cluster.arrive.aligned;" ::: "memory");
    asm volatile("barrier.cluster.wait.aligned;" ::: "memory");
}

// ---------------- K0: W^T and bias ------------------------------------------
__global__ void hmm_k0(const float* __restrict__ py) {
    int h = blockIdx.x * 8 + (threadIdx.x >> 5);
    int lane = threadIdx.x & 31;
    float s = 0.f;
#pragma unroll
    for (int c = 0; c < 4; c++) {
        int d = lane + c * 32;
        float p = __ldg(py + (size_t)h * Dn + d);
        float l1 = log1pf(-p);
        g_Wt[(size_t)d * Hn + h] = logf(p) - l1;
        s += l1;
    }
#pragma unroll
    for (int o = 16; o; o >>= 1) s += __shfl_xor_sync(0xffffffffu, s, o);
    if (lane == 0) g_bias[h] = s;
}

// ---------------- K1: emission GEMM  emit[t][n][h] = seq[n,t,:]*W^T + b ------
#define K1_SMEM ((64 * 132 + 128 * 128) * 4)
__global__ void __launch_bounds__(256) hmm_k1(const float* __restrict__ seq) {
    extern __shared__ float sm1[];
    float* seq_s = sm1;              // [64][132]
    float* W_s   = sm1 + 64 * 132;   // [128 k][128 h]

    int tid = threadIdx.x;
    int tb = blockIdx.y;
    int h0 = blockIdx.x * 128;

    for (int idx = tid; idx < 64 * 32; idx += 256) {
        int n = idx >> 5, d4 = idx & 31;
        float4 v = __ldg((const float4*)(seq + ((size_t)n * Tn + tb) * Dn + d4 * 4));
        *(float4*)&seq_s[n * 132 + d4 * 4] = v;
    }
    for (int idx = tid; idx < 128 * 32; idx += 256) {
        int k = idx >> 5, h4 = idx & 31;
        float4 v = __ldg((const float4*)(g_Wt + (size_t)k * Hn + h0 + h4 * 4));
        *(float4*)&W_s[k * 128 + h4 * 4] = v;
    }
    __syncthreads();

    int tx = tid & 15;
    int ty = tid >> 4;
    float acc[4][8];
#pragma unroll
    for (int u = 0; u < 4; u++)
#pragma unroll
        for (int v = 0; v < 8; v++) acc[u][v] = 0.f;

#pragma unroll 4
    for (int k = 0; k < 128; k++) {
        float aa[4];
#pragma unroll
        for (int u = 0; u < 4; u++) aa[u] = seq_s[(ty * 4 + u) * 132 + k];
        float4 b0 = *(const float4*)&W_s[k * 128 + tx * 8];
        float4 b1 = *(const float4*)&W_s[k * 128 + tx * 8 + 4];
        float bb[8] = {b0.x, b0.y, b0.z, b0.w, b1.x, b1.y, b1.z, b1.w};
#pragma unroll
        for (int u = 0; u < 4; u++)
#pragma unroll
            for (int v = 0; v < 8; v++) acc[u][v] = fmaf(aa[u], bb[v], acc[u][v]);
    }

    float4 bi0 = *(const float4*)&g_bias[h0 + tx * 8];
    float4 bi1 = *(const float4*)&g_bias[h0 + tx * 8 + 4];
    float bb[8] = {bi0.x, bi0.y, bi0.z, bi0.w, bi1.x, bi1.y, bi1.z, bi1.w};
#pragma unroll
    for (int u = 0; u < 4; u++) {
        size_t r = (size_t)tb * 64 + ty * 4 + u;
        float4 o0 = make_float4(acc[u][0] + bb[0], acc[u][1] + bb[1],
                                acc[u][2] + bb[2], acc[u][3] + bb[3]);
        float4 o1 = make_float4(acc[u][4] + bb[4], acc[u][5] + bb[5],
                                acc[u][6] + bb[6], acc[u][7] + bb[7]);
        *(float4*)&g_E[r * Hn + h0 + tx * 8]     = o0;
        *(float4*)&g_E[r * Hn + h0 + tx * 8 + 4] = o1;
    }
}

// ---------------- K2: rowmax + exp(emit - m), in place; write m --------------
__global__ void __launch_bounds__(256) hmm_k2() {
    int r = blockIdx.x * 8 + (threadIdx.x >> 5);
    int lane = threadIdx.x & 31;
    float* row = g_E + (size_t)r * Hn;
    float4 v[4];
    float m = -3.0e38f;
#pragma unroll
    for (int c = 0; c < 4; c++) {
        v[c] = *(const float4*)(row + c * 128 + lane * 4);
        m = fmaxf(m, fmaxf(fmaxf(v[c].x, v[c].y), fmaxf(v[c].z, v[c].w)));
    }
#pragma unroll
    for (int o = 16; o; o >>= 1) m = fmaxf(m, __shfl_xor_sync(0xffffffffu, m, o));
#pragma unroll
    for (int c = 0; c < 4; c++) {
        float4 e = make_float4(__expf(v[c].x - m), __expf(v[c].y - m),
                               __expf(v[c].z - m), __expf(v[c].w - m));
        *(float4*)(row + c * 128 + lane * 4) = e;
    }
    if (lane == 0) g_M[r] = m;
}

// ---------------- K3: two interleaved chains per cluster ---------------------
// Cluster = 4 seqs: chain0 {n0,n0+1}, chain1 {n0+2,n0+3}.
// dot: warp w = i-chunk [64w,64w+64), lane j-cols {lane, lane+32} (local).
// combine owners: lane<8 of every warp: seq-in-chain ws=w&1, j-pair jp=(w>>1)*8+lane.
__global__ void __launch_bounds__(256, 1) __cluster_dims__(K3_CL, 1, 1)
hmm_k3(const float* __restrict__ px, const int* __restrict__ lengths,
       float* __restrict__ out) {
    __shared__ float buf[2][2][2][AP];      // [chain][phase][seq][col]
    __shared__ float rsum[2][128 * 9];      // [chain][(s*64+j)*9 + chunk]
    __shared__ float ssum[2][2][8];         // [chain][seq][chunk-warp]
    __shared__ int   len_s[4];
    __shared__ float Cfin[4];
    __shared__ unsigned long long mbar[4];  // [chain*2 + phase]

    const int tid  = threadIdx.x;
    const int w    = tid >> 5;
    const int lane = tid & 31;
    unsigned rank;
    asm("mov.u32 %0, %%cluster_ctarank;" : "=r"(rank));
    const int grp = blockIdx.x >> 3;
    const int n0  = grp * 4;

    // dot j-columns
    const int jg0 = (int)rank * 64 + lane;
    const int jg1 = jg0 + 32;
    // combine-owner identity
    const bool owner = (lane < 8);
    const int  ws    = w & 1;                   // seq within chain
    const int  jp    = (w >> 1) * 8 + lane;     // j-pair 0..31
    const int  jloc  = 2 * jp;
    const int  jglob = (int)rank * 64 + jloc;
    const bool book  = (rank == 0 && lane == 0 && w < 2);

    unsigned mbo[4];
#pragma unroll
    for (int i = 0; i < 4; i++) mbo[i] = smem_u32(&mbar[i]);

    // P slice -> registers (same layout as R13)
    unsigned long long Pp[2][32];
#pragma unroll
    for (int k = 0; k < 32; k++) {
        const float* pr0 = px + (size_t)(w * 64 + 2 * k) * Hn;
        const float* pr1 = px + (size_t)(w * 64 + 2 * k + 1) * Hn;
        Pp[0][k] = pack2(__ldg(pr0 + jg0), __ldg(pr1 + jg0));
        Pp[1][k] = pack2(__ldg(pr0 + jg1), __ldg(pr1 + jg1));
    }
    if (tid == 0)
#pragma unroll
        for (int i = 0; i < 4; i++) mbar_init(mbo[i], 1);
    if (tid < 4) len_s[tid] = __ldg(lengths + n0 + tid);
    __syncthreads();
    if (tid == 0)
#pragma unroll
        for (int i = 0; i < 4; i++) mbar_expect(mbo[i], RX_BYTES);
    cluster_sync_hw();                          // inits visible cluster-wide

    unsigned aoff[2][2];
    if (owner)
#pragma unroll
        for (int c = 0; c < 2; c++)
#pragma unroll
            for (int p = 0; p < 2; p++)
                aoff[c][p] = smem_u32(&buf[c][p][ws][jglob]);

    float2 accv0 = make_float2(0.f, 0.f), accv1 = make_float2(0.f, 0.f);
    float  Creg0 = 0.f, Creg1 = 0.f;

    // ---- t = 0 init + push for both chains ----
    if (owner) {
#pragma unroll
        for (int c = 0; c < 2; c++) {
            float2& A = c ? accv1 : accv0;
            float2 e0 = __ldcg((const float2*)(g_E + (size_t)(n0 + 2 * c + ws) * Hn + jglob));
            A.x = __ldg(px + jglob) * e0.x;
            A.y = __ldg(px + jglob + 1) * e0.y;
            unsigned long long pk = pack2(A.x, A.y);
#pragma unroll
            for (unsigned i = 0; i < 8u; i++)
                st_async_b64(aoff[c][0], mbo[c * 2], (rank + i) & 7u, pk);
        }
    }
    if (book) {
        Creg0 = __ldg(g_M + n0 + w);
        Creg1 = __ldg(g_M + n0 + 2 + w);
    }

    // per-chain step (c is a compile-time-ish literal at each call site)
    auto chain_step = [&](int c, int t, float2& A, float& C) {
        const int rp = (t - 1) & 1;
        const int pb = t & 1;
        const unsigned parity = (unsigned)(((t - 1) >> 1) & 1);
        const int sg = n0 + 2 * c + ws;          // my seq (owners)

        float2 e = make_float2(0.f, 0.f);
        float mreg = 0.f;
        if (owner) {
            e = __ldcg((const float2*)(g_E + ((size_t)t * Nn + sg) * Hn + jglob));
            if (book) mreg = __ldg(g_M + (size_t)t * Nn + sg);
        }

        mbar_wait(mbo[c * 2 + rp], parity);
        if (tid == (c ? 208 : 240)) mbar_expect(mbo[c * 2 + rp], RX_BYTES);

        // dot over 64-i chunk for both chain seqs; also chunk sums for S
        unsigned long long q00 = 0ull, q01 = 0ull, q10 = 0ull, q11 = 0ull;
        unsigned long long sa0 = 0ull, sa1 = 0ull;
        {
            const ulonglong2* an0 = (const ulonglong2*)&buf[c][rp][0][w << 6];
            const ulonglong2* an1 = (const ulonglong2*)&buf[c][rp][1][w << 6];
#pragma unroll
            for (int k = 0; k < 16; k++) {
                ulonglong2 a0 = an0[k], a1 = an1[k];
                q00 = ffma2(a0.x, Pp[0][2 * k], q00);
                q00 = ffma2(a0.y, Pp[0][2 * k + 1], q00);
                q01 = ffma2(a0.x, Pp[1][2 * k], q01);
                q01 = ffma2(a0.y, Pp[1][2 * k + 1], q01);
                q10 = ffma2(a1.x, Pp[0][2 * k], q10);
                q10 = ffma2(a1.y, Pp[0][2 * k + 1], q10);
                q11 = ffma2(a1.x, Pp[1][2 * k], q11);
                q11 = ffma2(a1.y, Pp[1][2 * k + 1], q11);
                sa0 = fadd2(fadd2(sa0, a0.x), a0.y);
                sa1 = fadd2(fadd2(sa1, a1.x), a1.y);
            }
        }
        {
            float2 f;
            f = up2(q00); rsum[c][(lane) * 9 + w]        = f.x + f.y;
            f = up2(q01); rsum[c][(lane + 32) * 9 + w]   = f.x + f.y;
            f = up2(q10); rsum[c][(64 + lane) * 9 + w]   = f.x + f.y;
            f = up2(q11); rsum[c][(96 + lane) * 9 + w]   = f.x + f.y;
            if (lane == 0) {
                float2 s0 = up2(sa0), s1 = up2(sa1);
                ssum[c][0][w] = s0.x + s0.y;
                ssum[c][1][w] = s1.x + s1.y;
            }
        }
        __syncthreads();

        if (owner) {
            float S = 0.f;
#pragma unroll
            for (int cc = 0; cc < 8; cc++) S += ssum[c][ws][cc];
            float Rv = 1.0f / S;
            if (book && t < len_s[2 * c + ws]) C += __logf(S) + mreg;
            float t0 = 0.f, t1 = 0.f;
            const float* r0 = rsum[c] + (ws * 64 + jloc) * 9;
#pragma unroll
            for (int cc = 0; cc < 8; cc++) { t0 += r0[cc]; t1 += r0[9 + cc]; }
            float v0 = t0 * Rv * e.x, v1 = t1 * Rv * e.y;
            if (t < len_s[2 * c + ws]) { A.x = v0; A.y = v1; }
            unsigned long long pk = pack2(A.x, A.y);
#pragma unroll
            for (unsigned i = 0; i < 8u; i++)
                st_async_b64(aoff[c][pb], mbo[c * 2 + pb], (rank + i) & 7u, pk);
        }
    };

    for (int t = 1; t < Tn; t++) {
        chain_step(0, t, accv0, Creg0);
        chain_step(1, t, accv1, Creg1);
    }

    // drain both chains' final phase (all t=511 deliveries complete)
    mbar_wait(mbo[1], 1u);
    mbar_wait(mbo[3], 1u);

    if (book) { Cfin[w] = Creg0; Cfin[2 + w] = Creg1; }
    __syncthreads();

    // output: rank 0, warps 0-3 <-> sequences n0..n0+3
    if (rank == 0 && w < 4) {
        const float* ar = &buf[w >> 1][1][w & 1][0];
        float s = 0.f;
#pragma unroll
        for (int cc = 0; cc < 4; cc++) {
            float4 v = *(const float4*)(ar + cc * 128 + lane * 4);
            s += (v.x + v.y) + (v.z + v.w);
        }
#pragma unroll
        for (int o = 16; o; o >>= 1) s += __shfl_xor_sync(0xffffffffu, s, o);
        if (lane == 0) out[n0 + w] = Cfin[w] + logf(s);
    }
    cluster_sync_hw();                          // no early smem teardown
}

// ---------------- launch ------------------------------------------------------
extern "C" void kernel_launch(void* const* d_in, const int* in_sizes, int n_in,
                              void* d_out, int out_size) {
    const float* seq = nullptr;
    const int*   len = nullptr;
    const float* px  = nullptr;
    const float* py  = nullptr;
    for (int i = 0; i < n_in; i++) {
        switch (in_sizes[i]) {
            case Nn * Tn * Dn: seq = (const float*)d_in[i]; break;
            case Nn:           len = (const int*)d_in[i];   break;
            case Hn * Hn:      px  = (const float*)d_in[i]; break;
            case Hn * Dn:      py  = (const float*)d_in[i]; break;
        }
    }

    cudaFuncSetAttribute(hmm_k1, cudaFuncAttributeMaxDynamicSharedMemorySize, K1_SMEM);

    hmm_k0<<<64, 256>>>(py);
    hmm_k1<<<dim3(4, 512), 256, K1_SMEM>>>(seq);
    hmm_k2<<<4096, 256>>>();
    hmm_k3<<<16 * K3_CL, 256>>>(px, len, (float*)d_out);
}

// round 15
// speedup vs baseline: 1.1293x; 1.1293x over previous
#include <cuda_runtime.h>
#include <cuda_bf16.h>
#include <math.h>

// Problem dims
#define Hn 512
#define Dn 128
#define Nn 64
#define Tn 512

// K3 topology: 16 clusters x 8 CTAs. Cluster = 1 group of 4 sequences.
#define K3_CL 8
#define K3_NP 4
#define K3_JC 64
#define AP    516                 // buf row stride (floats), 16B-aligned
// count-based barrier: 4 owner-warps x 8 source CTAs = 32 arrivals per phase
#define ARRIVALS 32u

// ---------------- device scratch (static globals: no allocation) -------------
__device__ float g_E[(size_t)Tn * Nn * Hn];   // emit, then exp(emit - m); [t][n][h]
__device__ float g_M[Tn * Nn];                // rowmax m[t][n]
__device__ float g_Wt[Dn * Hn];               // W^T: [d][h]
__device__ float g_bias[Hn];

// ---------------- helpers -----------------------------------------------------
__device__ __forceinline__ unsigned long long ffma2(unsigned long long a,
                                                    unsigned long long b,
                                                    unsigned long long c) {
    unsigned long long d;
    asm("fma.rn.f32x2 %0, %1, %2, %3;" : "=l"(d) : "l"(a), "l"(b), "l"(c));
    return d;
}
__device__ __forceinline__ float2 up2(unsigned long long v) {
    float2 r;
    asm("mov.b64 {%0, %1}, %2;" : "=f"(r.x), "=f"(r.y) : "l"(v));
    return r;
}
__device__ __forceinline__ unsigned long long pack2(float lo, float hi) {
    unsigned long long v;
    asm("mov.b64 %0, {%1, %2};" : "=l"(v) : "f"(lo), "f"(hi));
    return v;
}
__device__ __forceinline__ unsigned smem_u32(const void* p) {
    return (unsigned)__cvta_generic_to_shared(p);
}
__device__ __forceinline__ unsigned mapa_rank(unsigned saddr, unsigned rank) {
    unsigned r;
    asm("mapa.shared::cluster.u32 %0, %1, %2;" : "=r"(r) : "r"(saddr), "r"(rank));
    return r;
}
// Plain (non-async-proxy) remote DSMEM stores.
__device__ __forceinline__ void st_cluster_b64(unsigned laddr, unsigned rank,
                                               unsigned long long v) {
    unsigned ra = mapa_rank(laddr, rank);
    asm volatile("st.shared::cluster.b64 [%0], %1;" :: "r"(ra), "l"(v) : "memory");
}
__device__ __forceinline__ void st_cluster_f32(unsigned laddr, unsigned rank, float v) {
    unsigned ra = mapa_rank(laddr, rank);
    asm volatile("st.shared::cluster.f32 [%0], %1;" :: "r"(ra), "f"(v) : "memory");
}
__device__ __forceinline__ void mbar_init(unsigned mbar, unsigned count) {
    asm volatile("mbarrier.init.shared.b64 [%0], %1;" :: "r"(mbar), "r"(count) : "memory");
}
// Remote release-arrive: orders this thread's prior cluster stores (and, via the
// preceding __syncwarp, the whole warp's) before the receiver's acquire-wait.
__device__ __forceinline__ void mbar_arrive_remote(unsigned lmbar, unsigned rank) {
    unsigned rb = mapa_rank(lmbar, rank);
    asm volatile("mbarrier.arrive.release.cluster.shared::cluster.b64 _, [%0];"
                 :: "r"(rb) : "memory");
}
__device__ __forceinline__ void mbar_wait(unsigned mbar, unsigned parity) {
    asm volatile(
        "{\n\t.reg .pred P1;\n\t"
        "WL_%=:\n\t"
        "mbarrier.try_wait.parity.acquire.cluster.shared::cta.b64 P1, [%0], %1, 0x989680;\n\t"
        "@P1 bra.uni WD_%=;\n\t"
        "bra.uni WL_%=;\n\t"
        "WD_%=:\n\t}"
        :: "r"(mbar), "r"(parity) : "memory");
}
__device__ __forceinline__ void cluster_sync_hw() {
    asm volatile("barrier.cluster.arrive.aligned;" ::: "memory");
    asm volatile("barrier.cluster.wait.aligned;" ::: "memory");
}

// ---------------- K0: W^T and bias ------------------------------------------
__global__ void hmm_k0(const float* __restrict__ py) {
    int h = blockIdx.x * 8 + (threadIdx.x >> 5);
    int lane = threadIdx.x & 31;
    float s = 0.f;
#pragma unroll
    for (int c = 0; c < 4; c++) {
        int d = lane + c * 32;
        float p = __ldg(py + (size_t)h * Dn + d);
        float l1 = log1pf(-p);
        g_Wt[(size_t)d * Hn + h] = logf(p) - l1;
        s += l1;
    }
#pragma unroll
    for (int o = 16; o; o >>= 1) s += __shfl_xor_sync(0xffffffffu, s, o);
    if (lane == 0) g_bias[h] = s;
}

// ---------------- K1: emission GEMM  emit[t][n][h] = seq[n,t,:]*W^T + b ------
#define K1_SMEM ((64 * 132 + 128 * 128) * 4)
__global__ void __launch_bounds__(256) hmm_k1(const float* __restrict__ seq) {
    extern __shared__ float sm1[];
    float* seq_s = sm1;              // [64][132]
    float* W_s   = sm1 + 64 * 132;   // [128 k][128 h]

    int tid = threadIdx.x;
    int tb = blockIdx.y;
    int h0 = blockIdx.x * 128;

    for (int idx = tid; idx < 64 * 32; idx += 256) {
        int n = idx >> 5, d4 = idx & 31;
        float4 v = __ldg((const float4*)(seq + ((size_t)n * Tn + tb) * Dn + d4 * 4));
        *(float4*)&seq_s[n * 132 + d4 * 4] = v;
    }
    for (int idx = tid; idx < 128 * 32; idx += 256) {
        int k = idx >> 5, h4 = idx & 31;
        float4 v = __ldg((const float4*)(g_Wt + (size_t)k * Hn + h0 + h4 * 4));
        *(float4*)&W_s[k * 128 + h4 * 4] = v;
    }
    __syncthreads();

    int tx = tid & 15;
    int ty = tid >> 4;
    float acc[4][8];
#pragma unroll
    for (int u = 0; u < 4; u++)
#pragma unroll
        for (int v = 0; v < 8; v++) acc[u][v] = 0.f;

#pragma unroll 4
    for (int k = 0; k < 128; k++) {
        float aa[4];
#pragma unroll
        for (int u = 0; u < 4; u++) aa[u] = seq_s[(ty * 4 + u) * 132 + k];
        float4 b0 = *(const float4*)&W_s[k * 128 + tx * 8];
        float4 b1 = *(const float4*)&W_s[k * 128 + tx * 8 + 4];
        float bb[8] = {b0.x, b0.y, b0.z, b0.w, b1.x, b1.y, b1.z, b1.w};
#pragma unroll
        for (int u = 0; u < 4; u++)
#pragma unroll
            for (int v = 0; v < 8; v++) acc[u][v] = fmaf(aa[u], bb[v], acc[u][v]);
    }

    float4 bi0 = *(const float4*)&g_bias[h0 + tx * 8];
    float4 bi1 = *(const float4*)&g_bias[h0 + tx * 8 + 4];
    float bb[8] = {bi0.x, bi0.y, bi0.z, bi0.w, bi1.x, bi1.y, bi1.z, bi1.w};
#pragma unroll
    for (int u = 0; u < 4; u++) {
        size_t r = (size_t)tb * 64 + ty * 4 + u;
        float4 o0 = make_float4(acc[u][0] + bb[0], acc[u][1] + bb[1],
                                acc[u][2] + bb[2], acc[u][3] + bb[3]);
        float4 o1 = make_float4(acc[u][4] + bb[4], acc[u][5] + bb[5],
                                acc[u][6] + bb[6], acc[u][7] + bb[7]);
        *(float4*)&g_E[r * Hn + h0 + tx * 8]     = o0;
        *(float4*)&g_E[r * Hn + h0 + tx * 8 + 4] = o1;
    }
}

// ---------------- K2: rowmax + exp(emit - m), in place; write m --------------
__global__ void __launch_bounds__(256) hmm_k2() {
    int r = blockIdx.x * 8 + (threadIdx.x >> 5);
    int lane = threadIdx.x & 31;
    float* row = g_E + (size_t)r * Hn;
    float4 v[4];
    float m = -3.0e38f;
#pragma unroll
    for (int c = 0; c < 4; c++) {
        v[c] = *(const float4*)(row + c * 128 + lane * 4);
        m = fmaxf(m, fmaxf(fmaxf(v[c].x, v[c].y), fmaxf(v[c].z, v[c].w)));
    }
#pragma unroll
    for (int o = 16; o; o >>= 1) m = fmaxf(m, __shfl_xor_sync(0xffffffffu, m, o));
#pragma unroll
    for (int c = 0; c < 4; c++) {
        float4 e = make_float4(__expf(v[c].x - m), __expf(v[c].y - m),
                               __expf(v[c].z - m), __expf(v[c].w - m));
        *(float4*)(row + c * 128 + lane * 4) = e;
    }
    if (lane == 0) g_M[r] = m;
}

// ---------------- K3: cluster scaled-forward (plain DSMEM st + count mbar) ---
// Roles (identical to R13):
//   dot:     all 8 warps; warp w: i-chunk [64w,64w+64), j-cols {lane, lane+32}
//   combine: tid < 128: warp w(<4) = sequence, lane: j-pair {2*lane, 2*lane+1}
__global__ void __launch_bounds__(256, 1) __cluster_dims__(K3_CL, 1, 1)
hmm_k3(const float* __restrict__ px, const int* __restrict__ lengths,
       float* __restrict__ out) {
    __shared__ float buf[2][K3_NP][AP];     // incoming alpha, double-buffered
    __shared__ float rsum[256 * 9];         // partials [(s*64+jloc)*9 + chunk]
    __shared__ float ps[2][K3_CL][K3_NP];   // per-rank per-seq partial sums
    __shared__ float R_s[K3_NP];            // 1/S per sequence
    __shared__ int   len_s[K3_NP];
    __shared__ unsigned long long mbar[2];

    const int tid  = threadIdx.x;
    const int w    = tid >> 5;
    const int lane = tid & 31;
    unsigned rank;
    asm("mov.u32 %0, %%cluster_ctarank;" : "=r"(rank));
    const int grp = blockIdx.x >> 3;             // cluster id 0..15
    const int n0  = grp * K3_NP;

    // combine-owner identity (tid < 128): seq = w, j-pair = 2*lane
    const bool owner = (w < K3_NP);
    const int  jloc  = 2 * lane;                 // even local column
    const int  jglob = (int)rank * K3_JC + jloc;
    // dot identity j-columns
    const int jg0 = (int)rank * K3_JC + lane;
    const int jg1 = jg0 + 32;

    const unsigned mb0 = smem_u32(&mbar[0]);
    const unsigned mb1 = smem_u32(&mbar[1]);

    // P slice -> registers: Pp[j][k] packs P[64w+2k][jg_j], P[64w+2k+1][jg_j]
    unsigned long long Pp[2][32];
#pragma unroll
    for (int k = 0; k < 32; k++) {
        const float* pr0 = px + (size_t)(w * 64 + 2 * k) * Hn;
        const float* pr1 = px + (size_t)(w * 64 + 2 * k + 1) * Hn;
        Pp[0][k] = pack2(__ldg(pr0 + jg0), __ldg(pr1 + jg0));
        Pp[1][k] = pack2(__ldg(pr0 + jg1), __ldg(pr1 + jg1));
    }
    if (tid == 0) {
        mbar_init(mb0, ARRIVALS);
        mbar_init(mb1, ARRIVALS);
    }
    if (tid < K3_NP) len_s[tid] = __ldg(lengths + n0 + tid);
    __syncthreads();
    const int mylen = owner ? len_s[w] : 0;
    cluster_sync_hw();                            // one-time: inits visible

    // push addresses (local-equivalent offsets, same in every rank)
    const unsigned a_off0 = owner ? smem_u32(&buf[0][w][jglob]) : 0u;
    const unsigned a_off1 = owner ? smem_u32(&buf[1][w][jglob]) : 0u;
    const unsigned p_off0 = smem_u32(&ps[0][rank][w & 3]);
    const unsigned p_off1 = smem_u32(&ps[1][rank][w & 3]);

    const bool scomp = (owner && lane == 0);      // per-CTA S/R computers
    const bool book  = (rank == 0 && scomp);      // bookkeeping (seq = w)
    float Creg = 0.f;
    if (book) Creg = __ldg(g_M + n0 + w);

    // ---- t = 0: alpha0 = px[0][j] * E0; push everywhere ----
    float2 accv = make_float2(0.f, 0.f);
    if (owner) {
        float2 e0 = __ldcg((const float2*)(g_E + (size_t)(n0 + w) * Hn + jglob));
        accv.x = __ldg(px + jglob) * e0.x;
        accv.y = __ldg(px + jglob + 1) * e0.y;
        unsigned long long pk = pack2(accv.x, accv.y);
#pragma unroll
        for (unsigned i = 0; i < K3_CL; i++)
            st_cluster_b64(a_off0, (rank + i) & 7u, pk);
        float psv = accv.x + accv.y;
#pragma unroll
        for (int o = 16; o; o >>= 1) psv += __shfl_xor_sync(0xffffffffu, psv, o);
        if (lane == 0)
#pragma unroll
            for (unsigned i = 0; i < K3_CL; i++)
                st_cluster_f32(p_off0, (rank + i) & 7u, psv);
        __syncwarp();
        if (lane < 8) mbar_arrive_remote(mb0, (rank + lane) & 7u);
    }

    for (int t = 1; t < Tn; t++) {
        const int rp = (t - 1) & 1;               // read buffer / barrier
        const int pb = t & 1;                     // push buffer / barrier
        const unsigned mbr = rp ? mb1 : mb0;
        const unsigned mbp = pb ? mb1 : mb0;
        const unsigned parity = (unsigned)(((t - 1) >> 1) & 1);

        // prefetches (independent of exchanged data)
        float2 e = make_float2(0.f, 0.f);
        float mreg = 0.f;
        if (owner) {
            e = __ldcg((const float2*)(g_E + ((size_t)t * Nn + n0 + w) * Hn + jglob));
            if (lane == 0 && rank == 0)
                mreg = __ldg(g_M + (size_t)t * Nn + n0 + w);
        }

        mbar_wait(mbr, parity);                   // count-based, self-resetting

        // dot: q[s][j] over this warp's 64-i chunk (broadcast LDS.128)
        unsigned long long q[K3_NP][2];
#pragma unroll
        for (int s = 0; s < K3_NP; s++) { q[s][0] = 0ull; q[s][1] = 0ull; }
#pragma unroll
        for (int s = 0; s < K3_NP; s++) {
            const ulonglong2* an = (const ulonglong2*)&buf[rp][s][w << 6];
#pragma unroll
            for (int k = 0; k < 16; k++) {
                ulonglong2 av = an[k];
                q[s][0] = ffma2(av.x, Pp[0][2 * k],     q[s][0]);
                q[s][0] = ffma2(av.y, Pp[0][2 * k + 1], q[s][0]);
                q[s][1] = ffma2(av.x, Pp[1][2 * k],     q[s][1]);
                q[s][1] = ffma2(av.y, Pp[1][2 * k + 1], q[s][1]);
            }
        }
#pragma unroll
        for (int s = 0; s < K3_NP; s++) {
#pragma unroll
            for (int j = 0; j < 2; j++) {
                float2 f = up2(q[s][j]);
                rsum[(s * 64 + lane + j * 32) * 9 + w] = f.x + f.y;
            }
        }

        // S_{t-1} + bookkeeping (parallel with other warps' rsum stores)
        if (scomp) {
            float S = 0.f;
#pragma unroll
            for (int r = 0; r < K3_CL; r++) S += ps[rp][r][w];
            R_s[w] = 1.0f / S;
            if (book && t < len_s[w]) Creg += __logf(S) + mreg;
        }
        __syncthreads();

        // combine 8 chunks for j-pair, scale, push as one b64 per rank
        if (owner) {
            float t0 = 0.f, t1 = 0.f;
            const float* r0 = rsum + (w * 64 + jloc) * 9;
#pragma unroll
            for (int c = 0; c < 8; c++) { t0 += r0[c]; t1 += r0[9 + c]; }
            float Rv = R_s[w];
            float n0v = t0 * Rv * e.x;
            float n1v = t1 * Rv * e.y;
            if (t < mylen) { accv.x = n0v; accv.y = n1v; }   // frozen copy-through
            const unsigned ao = pb ? a_off1 : a_off0;
            unsigned long long pk = pack2(accv.x, accv.y);
#pragma unroll
            for (unsigned i = 0; i < K3_CL; i++)
                st_cluster_b64(ao, (rank + i) & 7u, pk);
            float psv = accv.x + accv.y;
#pragma unroll
            for (int o = 16; o; o >>= 1) psv += __shfl_xor_sync(0xffffffffu, psv, o);
            if (lane == 0) {
                const unsigned po = pb ? p_off1 : p_off0;
#pragma unroll
                for (unsigned i = 0; i < K3_CL; i++)
                    st_cluster_f32(po, (rank + i) & 7u, psv);
            }
            __syncwarp();
            if (lane < 8) mbar_arrive_remote(mbp, (rank + lane) & 7u);
        }
    }

    // drain final phase (t=511 pushes landed cluster-wide; same parity as R13)
    mbar_wait(mb1, 1u);

    if (book) {
        float S = 0.f;
#pragma unroll
        for (int r = 0; r < K3_CL; r++) S += ps[1][r][w];
        out[n0 + w] = Creg + logf(S);
    }
    cluster_sync_hw();                            // no early smem teardown
}

// ---------------- launch ------------------------------------------------------
extern "C" void kernel_launch(void* const* d_in, const int* in_sizes, int n_in,
                              void* d_out, int out_size) {
    const float* seq = nullptr;
    const int*   len = nullptr;
    const float* px  = nullptr;
    const float* py  = nullptr;
    for (int i = 0; i < n_in; i++) {
        switch (in_sizes[i]) {
            case Nn * Tn * Dn: seq = (const float*)d_in[i]; break;
            case Nn:           len = (const int*)d_in[i];   break;
            case Hn * Hn:      px  = (const float*)d_in[i]; break;
            case Hn * Dn:      py  = (const float*)d_in[i]; break;
        }
    }

    cudaFuncSetAttribute(hmm_k1, cudaFuncAttributeMaxDynamicSharedMemorySize, K1_SMEM);

    hmm_k0<<<64, 256>>>(py);
    hmm_k1<<<dim3(4, 512), 256, K1_SMEM>>>(seq);
    hmm_k2<<<4096, 256>>>();
    hmm_k3<<<16 * K3_CL, 256>>>(px, len, (float*)d_out);
}

// round 16
// speedup vs baseline: 2.6078x; 2.3092x over previous
#include <cuda_runtime.h>
#include <cuda_bf16.h>
#include <math.h>

// Problem dims
#define Hn 512
#define Dn 128
#define Nn 64
#define Tn 512

// K3 topology: 16 clusters x 8 CTAs. Cluster = 1 group of 4 sequences.
#define K3_CL 8
#define K3_NP 4
#define K3_JC 64
#define AP    516                 // buf row stride (floats), 16B-aligned
#define RXA_BYTES 1024u           // per-source-rank alpha: 128 b64 msgs * 8B
#define RXP_BYTES 128u            // ps: 8 ranks * 4 seqs * 4B

// ---------------- device scratch (static globals: no allocation) -------------
__device__ float g_E[(size_t)Tn * Nn * Hn];   // emit, then exp(emit - m); [t][n][h]
__device__ float g_M[Tn * Nn];                // rowmax m[t][n]
__device__ float g_Wt[Dn * Hn];               // W^T: [d][h]
__device__ float g_bias[Hn];

// ---------------- helpers -----------------------------------------------------
__device__ __forceinline__ unsigned long long ffma2(unsigned long long a,
                                                    unsigned long long b,
                                                    unsigned long long c) {
    unsigned long long d;
    asm("fma.rn.f32x2 %0, %1, %2, %3;" : "=l"(d) : "l"(a), "l"(b), "l"(c));
    return d;
}
__device__ __forceinline__ float2 up2(unsigned long long v) {
    float2 r;
    asm("mov.b64 {%0, %1}, %2;" : "=f"(r.x), "=f"(r.y) : "l"(v));
    return r;
}
__device__ __forceinline__ unsigned long long pack2(float lo, float hi) {
    unsigned long long v;
    asm("mov.b64 %0, {%1, %2};" : "=l"(v) : "f"(lo), "f"(hi));
    return v;
}
__device__ __forceinline__ unsigned smem_u32(const void* p) {
    return (unsigned)__cvta_generic_to_shared(p);
}
__device__ __forceinline__ unsigned mapa_rank(unsigned saddr, unsigned rank) {
    unsigned r;
    asm("mapa.shared::cluster.u32 %0, %1, %2;" : "=r"(r) : "r"(saddr), "r"(rank));
    return r;
}
// st.async with PRE-MAPPED remote addresses (mapa hoisted out of the loop).
__device__ __forceinline__ void st_async_b64_pre(unsigned raddr, unsigned rmbar,
                                                 unsigned long long v) {
    asm volatile(
        "st.async.shared::cluster.mbarrier::complete_tx::bytes.b64 [%0], %1, [%2];"
        :: "r"(raddr), "l"(v), "r"(rmbar) : "memory");
}
__device__ __forceinline__ void st_async_f32_pre(unsigned raddr, unsigned rmbar,
                                                 float v) {
    asm volatile(
        "st.async.shared::cluster.mbarrier::complete_tx::bytes.b32 [%0], %1, [%2];"
        :: "r"(raddr), "r"(__float_as_uint(v)), "r"(rmbar) : "memory");
}
__device__ __forceinline__ void mbar_init(unsigned mbar, unsigned count) {
    asm volatile("mbarrier.init.shared.b64 [%0], %1;" :: "r"(mbar), "r"(count) : "memory");
}
__device__ __forceinline__ void mbar_expect(unsigned mbar, unsigned bytes) {
    asm volatile("mbarrier.arrive.expect_tx.shared.b64 _, [%0], %1;"
                 :: "r"(mbar), "r"(bytes) : "memory");
}
// CTA-scope acquire: sufficient for st.async deliveries into OUR smem.
__device__ __forceinline__ void mbar_wait(unsigned mbar, unsigned parity) {
    asm volatile(
        "{\n\t.reg .pred P1;\n\t"
        "WL_%=:\n\t"
        "mbarrier.try_wait.parity.acquire.cta.shared::cta.b64 P1, [%0], %1, 0x989680;\n\t"
        "@P1 bra.uni WD_%=;\n\t"
        "bra.uni WL_%=;\n\t"
        "WD_%=:\n\t}"
        :: "r"(mbar), "r"(parity) : "memory");
}
__device__ __forceinline__ void cluster_sync_hw() {
    asm volatile("barrier.cluster.arrive.aligned;" ::: "memory");
    asm volatile("barrier.cluster.wait.aligned;" ::: "memory");
}

// ---------------- K0: W^T and bias ------------------------------------------
__global__ void hmm_k0(const float* __restrict__ py) {
    int h = blockIdx.x * 8 + (threadIdx.x >> 5);
    int lane = threadIdx.x & 31;
    float s = 0.f;
#pragma unroll
    for (int c = 0; c < 4; c++) {
        int d = lane + c * 32;
        float p = __ldg(py + (size_t)h * Dn + d);
        float l1 = log1pf(-p);
        g_Wt[(size_t)d * Hn + h] = logf(p) - l1;
        s += l1;
    }
#pragma unroll
    for (int o = 16; o; o >>= 1) s += __shfl_xor_sync(0xffffffffu, s, o);
    if (lane == 0) g_bias[h] = s;
}

// ---------------- K1: emission GEMM  emit[t][n][h] = seq[n,t,:]*W^T + b ------
#define K1_SMEM ((64 * 132 + 128 * 128) * 4)
__global__ void __launch_bounds__(256) hmm_k1(const float* __restrict__ seq) {
    extern __shared__ float sm1[];
    float* seq_s = sm1;              // [64][132]
    float* W_s   = sm1 + 64 * 132;   // [128 k][128 h]

    int tid = threadIdx.x;
    int tb = blockIdx.y;
    int h0 = blockIdx.x * 128;

    for (int idx = tid; idx < 64 * 32; idx += 256) {
        int n = idx >> 5, d4 = idx & 31;
        float4 v = __ldg((const float4*)(seq + ((size_t)n * Tn + tb) * Dn + d4 * 4));
        *(float4*)&seq_s[n * 132 + d4 * 4] = v;
    }
    for (int idx = tid; idx < 128 * 32; idx += 256) {
        int k = idx >> 5, h4 = idx & 31;
        float4 v = __ldg((const float4*)(g_Wt + (size_t)k * Hn + h0 + h4 * 4));
        *(float4*)&W_s[k * 128 + h4 * 4] = v;
    }
    __syncthreads();

    int tx = tid & 15;
    int ty = tid >> 4;
    float acc[4][8];
#pragma unroll
    for (int u = 0; u < 4; u++)
#pragma unroll
        for (int v = 0; v < 8; v++) acc[u][v] = 0.f;

#pragma unroll 4
    for (int k = 0; k < 128; k++) {
        float aa[4];
#pragma unroll
        for (int u = 0; u < 4; u++) aa[u] = seq_s[(ty * 4 + u) * 132 + k];
        float4 b0 = *(const float4*)&W_s[k * 128 + tx * 8];
        float4 b1 = *(const float4*)&W_s[k * 128 + tx * 8 + 4];
        float bb[8] = {b0.x, b0.y, b0.z, b0.w, b1.x, b1.y, b1.z, b1.w};
#pragma unroll
        for (int u = 0; u < 4; u++)
#pragma unroll
            for (int v = 0; v < 8; v++) acc[u][v] = fmaf(aa[u], bb[v], acc[u][v]);
    }

    float4 bi0 = *(const float4*)&g_bias[h0 + tx * 8];
    float4 bi1 = *(const float4*)&g_bias[h0 + tx * 8 + 4];
    float bb[8] = {bi0.x, bi0.y, bi0.z, bi0.w, bi1.x, bi1.y, bi1.z, bi1.w};
#pragma unroll
    for (int u = 0; u < 4; u++) {
        size_t r = (size_t)tb * 64 + ty * 4 + u;
        float4 o0 = make_float4(acc[u][0] + bb[0], acc[u][1] + bb[1],
                                acc[u][2] + bb[2], acc[u][3] + bb[3]);
        float4 o1 = make_float4(acc[u][4] + bb[4], acc[u][5] + bb[5],
                                acc[u][6] + bb[6], acc[u][7] + bb[7]);
        *(float4*)&g_E[r * Hn + h0 + tx * 8]     = o0;
        *(float4*)&g_E[r * Hn + h0 + tx * 8 + 4] = o1;
    }
}

// ---------------- K2: rowmax + exp(emit - m), in place; write m --------------
__global__ void __launch_bounds__(256) hmm_k2() {
    int r = blockIdx.x * 8 + (threadIdx.x >> 5);
    int lane = threadIdx.x & 31;
    float* row = g_E + (size_t)r * Hn;
    float4 v[4];
    float m = -3.0e38f;
#pragma unroll
    for (int c = 0; c < 4; c++) {
        v[c] = *(const float4*)(row + c * 128 + lane * 4);
        m = fmaxf(m, fmaxf(fmaxf(v[c].x, v[c].y), fmaxf(v[c].z, v[c].w)));
    }
#pragma unroll
    for (int o = 16; o; o >>= 1) m = fmaxf(m, __shfl_xor_sync(0xffffffffu, m, o));
#pragma unroll
    for (int c = 0; c < 4; c++) {
        float4 e = make_float4(__expf(v[c].x - m), __expf(v[c].y - m),
                               __expf(v[c].z - m), __expf(v[c].w - m));
        *(float4*)(row + c * 128 + lane * 4) = e;
    }
    if (lane == 0) g_M[r] = m;
}

// ---------------- K3: st.async scaled-forward, per-source-rank mbarriers -----
// Roles (as R13):
//   dot:     warp w: i-chunk [64w,64w+64)  == data pushed by source rank w
//   combine: tid < 128: warp w(<4) = sequence, lane: j-pair {2*lane, 2*lane+1}
__global__ void __launch_bounds__(256, 1) __cluster_dims__(K3_CL, 1, 1)
hmm_k3(const float* __restrict__ px, const int* __restrict__ lengths,
       float* __restrict__ out) {
    __shared__ float buf[2][K3_NP][AP];     // incoming alpha, double-buffered
    __shared__ float rsum[256 * 9];         // partials [(s*64+jloc)*9 + chunk]
    __shared__ float ps[2][K3_CL][K3_NP];   // per-rank per-seq partial sums
    __shared__ float R_s[K3_NP];            // 1/S per sequence
    __shared__ int   len_s[K3_NP];
    __shared__ unsigned long long mbarA[2][K3_CL];  // [phase][source rank]
    __shared__ unsigned long long mbarP[2];         // ps barriers

    const int tid  = threadIdx.x;
    const int w    = tid >> 5;
    const int lane = tid & 31;
    unsigned rank;
    asm("mov.u32 %0, %%cluster_ctarank;" : "=r"(rank));
    const int grp = blockIdx.x >> 3;             // cluster id 0..15
    const int n0  = grp * K3_NP;

    // combine-owner identity (tid < 128): seq = w, j-pair = 2*lane
    const bool owner = (w < K3_NP);
    const int  jloc  = 2 * lane;
    const int  jglob = (int)rank * K3_JC + jloc;
    // dot identity j-columns
    const int jg0 = (int)rank * K3_JC + lane;
    const int jg1 = jg0 + 32;

    // local mbar addresses
    const unsigned mbA_mine = smem_u32(&mbarA[0][w]);      // phase0; +64B = phase1
    const unsigned mbP0     = smem_u32(&mbarP[0]);
    const unsigned mbP1     = smem_u32(&mbarP[1]);

    // P slice -> registers
    unsigned long long Pp[2][32];
#pragma unroll
    for (int k = 0; k < 32; k++) {
        const float* pr0 = px + (size_t)(w * 64 + 2 * k) * Hn;
        const float* pr1 = px + (size_t)(w * 64 + 2 * k + 1) * Hn;
        Pp[0][k] = pack2(__ldg(pr0 + jg0), __ldg(pr1 + jg0));
        Pp[1][k] = pack2(__ldg(pr0 + jg1), __ldg(pr1 + jg1));
    }
    if (tid < 16) {                               // 16 alpha mbars
        mbar_init(smem_u32(&mbarA[tid >> 3][tid & 7]), 1);
        if (tid < 2) mbar_init(smem_u32(&mbarP[tid]), 1);
    }
    if (tid < K3_NP) len_s[tid] = __ldg(lengths + n0 + tid);
    __syncthreads();
    if (tid < 16) mbar_expect(smem_u32(&mbarA[tid >> 3][tid & 7]), RXA_BYTES);
    if (tid == 16) mbar_expect(mbP0, RXP_BYTES);
    if (tid == 17) mbar_expect(mbP1, RXP_BYTES);
    const int mylen = owner ? len_s[w] : 0;
    cluster_sync_hw();                            // inits+expects visible

    // ---- hoisted remote addresses (phase 0; phase 1 = constant offsets) ----
    // alpha data lands at the SAME local offset in every rank's buf.
    const unsigned BOFF = (unsigned)(K3_NP * AP * 4);   // buf[1]-buf[0] bytes
    unsigned ra_a[K3_CL], ra_am[K3_CL];           // owner: data addr + dest mbar
    unsigned ra_p[K3_CL], ra_pm[K3_CL];           // lane0 owners: ps addr + mbar
    if (owner) {
        const unsigned a_local  = smem_u32(&buf[0][w][jglob]);
        const unsigned am_local = smem_u32(&mbarA[0][rank]); // dest indexes SOURCE=my rank
#pragma unroll
        for (unsigned i = 0; i < K3_CL; i++) {
            unsigned r = (rank + i) & 7u;
            ra_a[i]  = mapa_rank(a_local, r);
            ra_am[i] = mapa_rank(am_local, r);
        }
        if (lane == 0) {
            const unsigned p_local = smem_u32(&ps[0][rank][w]);
#pragma unroll
            for (unsigned i = 0; i < K3_CL; i++) {
                unsigned r = (rank + i) & 7u;
                ra_p[i]  = mapa_rank(p_local, r);
                ra_pm[i] = mapa_rank(mbP0, r);
            }
        }
    }

    const bool scomp = (owner && lane == 0);
    const bool book  = (rank == 0 && scomp);
    float Creg = 0.f;
    if (book) Creg = __ldg(g_M + n0 + w);

    // ---- t = 0: alpha0 = px[0][j] * E0; push everywhere (phase 0) ----
    float2 accv = make_float2(0.f, 0.f);
    if (owner) {
        float2 e0 = __ldcg((const float2*)(g_E + (size_t)(n0 + w) * Hn + jglob));
        accv.x = __ldg(px + jglob) * e0.x;
        accv.y = __ldg(px + jglob + 1) * e0.y;
        unsigned long long pk = pack2(accv.x, accv.y);
#pragma unroll
        for (unsigned i = 0; i < K3_CL; i++)
            st_async_b64_pre(ra_a[i], ra_am[i], pk);
        float psv = accv.x + accv.y;
#pragma unroll
        for (int o = 16; o; o >>= 1) psv += __shfl_xor_sync(0xffffffffu, psv, o);
        if (lane == 0)
#pragma unroll
            for (unsigned i = 0; i < K3_CL; i++)
                st_async_f32_pre(ra_p[i], ra_pm[i], psv);
    }

    for (int t = 1; t < Tn; t++) {
        const int rp = (t - 1) & 1;               // read phase
        const int pb = t & 1;                     // push phase
        const unsigned parity = (unsigned)(((t - 1) >> 1) & 1);

        // prefetches
        float2 e = make_float2(0.f, 0.f);
        float mreg = 0.f;
        if (owner) {
            e = __ldcg((const float2*)(g_E + ((size_t)t * Nn + n0 + w) * Hn + jglob));
            if (lane == 0 && rank == 0)
                mreg = __ldg(g_M + (size_t)t * Nn + n0 + w);
        }

        // warp w waits ONLY for its source rank's delivery
        const unsigned mbw = mbA_mine + (unsigned)(rp * 64);
        mbar_wait(mbw, parity);
        if (lane == 0) mbar_expect(mbw, RXA_BYTES);   // re-arm for t+2

        // dot: q[s][j] over this warp's 64-i chunk (broadcast LDS.128)
        unsigned long long q[K3_NP][2];
#pragma unroll
        for (int s = 0; s < K3_NP; s++) { q[s][0] = 0ull; q[s][1] = 0ull; }
#pragma unroll
        for (int s = 0; s < K3_NP; s++) {
            const ulonglong2* an = (const ulonglong2*)&buf[rp][s][w << 6];
#pragma unroll
            for (int k = 0; k < 16; k++) {
                ulonglong2 av = an[k];
                q[s][0] = ffma2(av.x, Pp[0][2 * k],     q[s][0]);
                q[s][0] = ffma2(av.y, Pp[0][2 * k + 1], q[s][0]);
                q[s][1] = ffma2(av.x, Pp[1][2 * k],     q[s][1]);
                q[s][1] = ffma2(av.y, Pp[1][2 * k + 1], q[s][1]);
            }
        }
#pragma unroll
        for (int s = 0; s < K3_NP; s++) {
#pragma unroll
            for (int j = 0; j < 2; j++) {
                float2 f = up2(q[s][j]);
                rsum[(s * 64 + lane + j * 32) * 9 + w] = f.x + f.y;
            }
        }

        // S_{t-1}: scomp waits ps barrier (delivered long ago), computes R
        if (scomp) {
            const unsigned mbp_r = rp ? mbP1 : mbP0;
            mbar_wait(mbp_r, parity);
            if (w == 0) mbar_expect(mbp_r, RXP_BYTES);
            float S = 0.f;
#pragma unroll
            for (int r = 0; r < K3_CL; r++) S += ps[rp][r][w];
            R_s[w] = 1.0f / S;
            if (book && t < len_s[w]) Creg += __logf(S) + mreg;
        }
        __syncthreads();

        // combine 8 chunks for j-pair, scale, push one b64 per rank
        if (owner) {
            float t0 = 0.f, t1 = 0.f;
            const float* r0 = rsum + (w * 64 + jloc) * 9;
#pragma unroll
            for (int c = 0; c < 8; c++) { t0 += r0[c]; t1 += r0[9 + c]; }
            float Rv = R_s[w];
            float n0v = t0 * Rv * e.x;
            float n1v = t1 * Rv * e.y;
            if (t < mylen) { accv.x = n0v; accv.y = n1v; }
            const unsigned aoff = (unsigned)(pb ? BOFF : 0u);
            const unsigned moff = (unsigned)(pb ? 64u : 0u);
            unsigned long long pk = pack2(accv.x, accv.y);
#pragma unroll
            for (unsigned i = 0; i < K3_CL; i++)
                st_async_b64_pre(ra_a[i] + aoff, ra_am[i] + moff, pk);
            float psv = accv.x + accv.y;
#pragma unroll
            for (int o = 16; o; o >>= 1) psv += __shfl_xor_sync(0xffffffffu, psv, o);
            if (lane == 0) {
                const unsigned poff = (unsigned)(pb ? 128u : 0u);  // ps[1]-ps[0]
                const unsigned pmoff = (unsigned)(pb ? 8u : 0u);   // mbarP[1]-[0]
#pragma unroll
                for (unsigned i = 0; i < K3_CL; i++)
                    st_async_f32_pre(ra_p[i] + poff, ra_pm[i] + pmoff, psv);
            }
        }
    }

    // drain phase-1 barriers (final t=511 pushes; parity matches R13's mb1,1)
    mbar_wait(mbA_mine + 64u, 1u);
    if (scomp) mbar_wait(mbP1, 1u);

    if (book) {
        float S = 0.f;
#pragma unroll
        for (int r = 0; r < K3_CL; r++) S += ps[1][r][w];
        out[n0 + w] = Creg + logf(S);
    }
    cluster_sync_hw();                            // no early smem teardown
}

// ---------------- launch ------------------------------------------------------
extern "C" void kernel_launch(void* const* d_in, const int* in_sizes, int n_in,
                              void* d_out, int out_size) {
    const float* seq = nullptr;
    const int*   len = nullptr;
    const float* px  = nullptr;
    const float* py  = nullptr;
    for (int i = 0; i < n_in; i++) {
        switch (in_sizes[i]) {
            case Nn * Tn * Dn: seq = (const float*)d_in[i]; break;
            case Nn:           len = (const int*)d_in[i];   break;
            case Hn * Hn:      px  = (const float*)d_in[i]; break;
            case Hn * Dn:      py  = (const float*)d_in[i]; break;
        }
    }

    cudaFuncSetAttribute(hmm_k1, cudaFuncAttributeMaxDynamicSharedMemorySize, K1_SMEM);

    hmm_k0<<<64, 256>>>(py);
    hmm_k1<<<dim3(4, 512), 256, K1_SMEM>>>(seq);
    hmm_k2<<<4096, 256>>>();
    hmm_k3<<<16 * K3_CL, 256>>>(px, len, (float*)d_out);
}